// round 1
// baseline (speedup 1.0000x reference)
#include <cuda_runtime.h>
#include <math.h>

#define T 4096
#define S 256
#define G 128          // CTAs (<= 148 SMs -> co-resident, spin barrier safe)
#define BT 256         // threads per CTA (2 rows of 128)

// scratch (no cudaMalloc allowed)
__device__ int      g_bp[T * S];     // backpointers, 4 MB
__device__ unsigned g_cnt;           // global barrier counter (monotonic)

__device__ __forceinline__ unsigned ld_acq(const unsigned* p) {
    unsigned v;
    asm volatile("ld.acquire.gpu.global.u32 %0, [%1];" : "=r"(v) : "l"(p));
    return v;
}
__device__ __forceinline__ void red_rel_add1(unsigned* p) {
    asm volatile("red.release.gpu.global.add.u32 [%0], %1;" :: "l"(p), "r"(1u) : "memory");
}

__global__ void sv_init_kernel() {
    if (threadIdx.x == 0) g_cnt = 0u;
}

__global__ __launch_bounds__(BT, 1)
void sv_dp_kernel(const float* __restrict__ pot, float* __restrict__ out) {
    float* vout = out + T;            // v[t*S + s], row-major (T,S)

    const int tid  = threadIdx.x;
    const int row  = tid >> 7;        // 0 or 1 (which of the CTA's 2 rows)
    const int rtid = tid & 127;       // thread index within row group
    const int lane = tid & 31;
    const int wir  = rtid >> 5;       // warp-in-row 0..3
    const int s    = (blockIdx.x << 1) + row;   // this row's state index

    __shared__ float s_m[2][4];
    __shared__ int   s_i[2][4];
    __shared__ float s_sum[2][4];

    // ---- step 0: v0 = potentials[0, 0, :]  (CTA 0 writes it) ----
    if (blockIdx.x == 0) {
        vout[tid] = pot[tid];         // tid = 0..255 covers s'
    }
    if (tid == 0) red_rel_add1(&g_cnt);   // arrive phase 1

    // prefetch potentials for t = 1 into registers
    const float* prow = pot + (size_t)s * S;
    float p0 = prow[(size_t)1 * S * S + rtid];
    float p1 = prow[(size_t)1 * S * S + rtid + 128];

    unsigned target = G;
    for (int t = 1; t < T; ++t) {
        // wait until everyone finished step t-1 (spin hides pot prefetch latency)
        if (tid == 0) { while (ld_acq(&g_cnt) < target) { } }
        __syncthreads();

        // scores[s, s'] = v_{t-1}[s'] + pot[t, s, s']
        float sv0 = vout[(size_t)(t - 1) * S + rtid];
        float sv1 = vout[(size_t)(t - 1) * S + rtid + 128];
        float sc0 = sv0 + p0;
        float sc1 = sv1 + p1;

        // thread-local max/argmax (first-index tie-break: rtid < rtid+128)
        float m;  int mi;
        if (sc1 > sc0) { m = sc1; mi = rtid + 128; } else { m = sc0; mi = rtid; }

        #pragma unroll
        for (int o = 16; o; o >>= 1) {
            float om = __shfl_xor_sync(0xffffffffu, m, o);
            int   oi = __shfl_xor_sync(0xffffffffu, mi, o);
            if (om > m || (om == m && oi < mi)) { m = om; mi = oi; }
        }
        if (lane == 0) { s_m[row][wir] = m; s_i[row][wir] = mi; }
        __syncthreads();

        m = s_m[row][0]; mi = s_i[row][0];
        #pragma unroll
        for (int w = 1; w < 4; ++w) {
            float om = s_m[row][w]; int oi = s_i[row][w];
            if (om > m || (om == m && oi < mi)) { m = om; mi = oi; }
        }

        // sum exp(score - m)
        float e = expf(sc0 - m) + expf(sc1 - m);
        #pragma unroll
        for (int o = 16; o; o >>= 1) e += __shfl_xor_sync(0xffffffffu, e, o);
        if (lane == 0) s_sum[row][wir] = e;
        __syncthreads();

        if (rtid == 0) {
            float sum = s_sum[row][0] + s_sum[row][1] + s_sum[row][2] + s_sum[row][3];
            vout[(size_t)t * S + s] = m + logf(sum);
            g_bp[t * S + s] = mi;
        }

        // prefetch potentials for t+1 (latency hidden by next barrier spin)
        if (t + 1 < T) {
            p0 = prow[(size_t)(t + 1) * S * S + rtid];
            p1 = prow[(size_t)(t + 1) * S * S + rtid + 128];
        }

        __syncthreads();                 // both rows' global writes done
        if (tid == 0) red_rel_add1(&g_cnt);
        target += G;
    }

    // ---- backtrace (CTA 0 only, after everyone finished) ----
    if (tid == 0) { while (ld_acq(&g_cnt) < (unsigned)G * T) { } }
    __syncthreads();
    if (blockIdx.x != 0) return;

    // argmax over v[T-1, :] (first max index)
    float m = vout[(size_t)(T - 1) * S + tid];
    int   mi = tid;
    #pragma unroll
    for (int o = 16; o; o >>= 1) {
        float om = __shfl_xor_sync(0xffffffffu, m, o);
        int   oi = __shfl_xor_sync(0xffffffffu, mi, o);
        if (om > m || (om == m && oi < mi)) { m = om; mi = oi; }
    }
    __shared__ float fm[8];
    __shared__ int   fi[8];
    if (lane == 0) { fm[tid >> 5] = m; fi[tid >> 5] = mi; }
    __syncthreads();
    if (tid == 0) {
        m = fm[0]; mi = fi[0];
        #pragma unroll
        for (int w = 1; w < 8; ++w)
            if (fm[w] > m || (fm[w] == m && fi[w] < mi)) { m = fm[w]; mi = fi[w]; }

        int cur = mi;
        out[T - 1] = (float)cur;
        for (int t = T - 2; t >= 0; --t) {
            cur = g_bp[(t + 1) * S + cur];
            out[t] = (float)cur;
        }
    }
}

extern "C" void kernel_launch(void* const* d_in, const int* in_sizes, int n_in,
                              void* d_out, int out_size) {
    const float* pot = (const float*)d_in[0];
    float* out = (float*)d_out;

    sv_init_kernel<<<1, 32>>>();
    sv_dp_kernel<<<G, BT>>>(pot, out);
}